// round 2
// baseline (speedup 1.0000x reference)
#include <cuda_runtime.h>

#define TOK   32768
#define DIN   1024
#define RDIM  128
#define NSLOT 4096
#define MAXK  32

// ---------------- scratch (static device arrays; no allocation) ----------------
__device__ float  g_hidden[TOK * RDIM];            // 16.8 MB
__device__ float4 g_scores_v[TOK * NSLOT / 4];     // 512 MB, 16B-aligned
__device__ float  g_m[TOK];
__device__ float  g_z[TOK];
__device__ int    g_budget[TOK];
__device__ float4 g_counts_v[NSLOT / 4];           // 16B-aligned counts
__device__ float  g_aux;

#define g_scores ((float*)g_scores_v)
#define g_counts ((float*)g_counts_v)

// ---------------- f32x2 helpers (Blackwell packed fp32 pipe) ----------------
__device__ __forceinline__ unsigned long long pack2(float lo, float hi) {
    unsigned long long r;
    asm("mov.b64 %0, {%1, %2};" : "=l"(r) : "f"(lo), "f"(hi));
    return r;
}
__device__ __forceinline__ void fma2(unsigned long long& d, unsigned long long a,
                                     unsigned long long b) {
    asm("fma.rn.f32x2 %0, %1, %2, %0;" : "+l"(d) : "l"(a), "l"(b));
}
__device__ __forceinline__ float2 unpack2(unsigned long long v) {
    float2 f;
    asm("mov.b64 {%0, %1}, %2;" : "=f"(f.x), "=f"(f.y) : "l"(v));
    return f;
}

// ---------------- reductions ----------------
__device__ __forceinline__ float warpReduceMaxF(float v) {
#pragma unroll
    for (int o = 16; o > 0; o >>= 1) v = fmaxf(v, __shfl_xor_sync(0xffffffffu, v, o));
    return v;
}
__device__ __forceinline__ float warpReduceSumF(float v) {
#pragma unroll
    for (int o = 16; o > 0; o >>= 1) v += __shfl_xor_sync(0xffffffffu, v, o);
    return v;
}
__device__ __forceinline__ unsigned long long warpReduceMaxU64(unsigned long long v) {
#pragma unroll
    for (int o = 16; o > 0; o >>= 1) {
        unsigned long long t = __shfl_xor_sync(0xffffffffu, v, o);
        v = (t > v) ? t : v;
    }
    return v;
}

// ---------------- K0: zero counts + aux ----------------
__global__ void k_init() {
    int i = blockIdx.x * blockDim.x + threadIdx.x;
    if (i < NSLOT) g_counts[i] = 0.f;
    if (i == 0)    g_aux = 0.f;
}

// ---------------- K1: hidden = relu(x @ W_h + b_h); budget from sigmoid(x@W_c+b_c) ----------------
__global__ __launch_bounds__(256) void k_hidden(
    const float* __restrict__ x,  const float* __restrict__ Wc, const float* __restrict__ bc,
    const float* __restrict__ Wh, const float* __restrict__ bh, float* __restrict__ out_b)
{
    __shared__ float Xs[32][132];   // transposed x tile [k][token]
    __shared__ float Wsm[32][128];  // W_h tile [k][n]
    __shared__ float Wcs[32];

    const int tid = threadIdx.x;
    const int tx = tid & 15, ty = tid >> 4;
    const int t0 = blockIdx.x * 128;

    // acc2[token i][col-pair jp]; jp<2 -> cols tx*4+2jp,+1 ; jp>=2 -> 64+tx*4+2(jp-2),+1
    unsigned long long acc2[8][4];
    {
        float b0a = bh[tx * 4 + 0], b0b = bh[tx * 4 + 1];
        float b1a = bh[tx * 4 + 2], b1b = bh[tx * 4 + 3];
        float b2a = bh[64 + tx * 4 + 0], b2b = bh[64 + tx * 4 + 1];
        float b3a = bh[64 + tx * 4 + 2], b3b = bh[64 + tx * 4 + 3];
        unsigned long long p0 = pack2(b0a, b0b), p1 = pack2(b1a, b1b);
        unsigned long long p2 = pack2(b2a, b2b), p3 = pack2(b3a, b3b);
#pragma unroll
        for (int i = 0; i < 8; i++) { acc2[i][0] = p0; acc2[i][1] = p1; acc2[i][2] = p2; acc2[i][3] = p3; }
    }
    float cacc = 0.f;

    for (int kt = 0; kt < 32; kt++) {
#pragma unroll
        for (int i = 0; i < 4; i++) {
            int id = tid + i * 256;
            int token = id >> 3, kg = id & 7;
            float4 f = *(const float4*)(x + (size_t)(t0 + token) * DIN + kt * 32 + kg * 4);
            Xs[kg * 4 + 0][token] = f.x; Xs[kg * 4 + 1][token] = f.y;
            Xs[kg * 4 + 2][token] = f.z; Xs[kg * 4 + 3][token] = f.w;
        }
#pragma unroll
        for (int i = 0; i < 4; i++) {
            int id = tid + i * 256;
            int rowk = id >> 5, ng = id & 31;
            *(float4*)&Wsm[rowk][ng * 4] =
                *(const float4*)(Wh + (size_t)(kt * 32 + rowk) * RDIM + ng * 4);
        }
        if (tid < 32) Wcs[tid] = Wc[kt * 32 + tid];
        __syncthreads();

#pragma unroll 4
        for (int k = 0; k < 32; k++) {
            float4 a0 = *(float4*)&Xs[k][ty * 4];
            float4 a1 = *(float4*)&Xs[k][64 + ty * 4];
            ulonglong2 w01 = *(ulonglong2*)&Wsm[k][tx * 4];
            ulonglong2 w23 = *(ulonglong2*)&Wsm[k][64 + tx * 4];
            float xf[8] = {a0.x, a0.y, a0.z, a0.w, a1.x, a1.y, a1.z, a1.w};
#pragma unroll
            for (int i = 0; i < 8; i++) {
                unsigned long long ad = pack2(xf[i], xf[i]);
                fma2(acc2[i][0], ad, w01.x);
                fma2(acc2[i][1], ad, w01.y);
                fma2(acc2[i][2], ad, w23.x);
                fma2(acc2[i][3], ad, w23.y);
            }
        }
        if (tid < 128) {
            float s = 0.f;
#pragma unroll
            for (int k = 0; k < 32; k++) s += Xs[k][tid] * Wcs[k];
            cacc += s;
        }
        __syncthreads();
    }

#pragma unroll
    for (int i = 0; i < 8; i++) {
        int r = (i < 4) ? ty * 4 + i : 64 + ty * 4 + (i - 4);
        float2 u0 = unpack2(acc2[i][0]), u1 = unpack2(acc2[i][1]);
        float2 u2 = unpack2(acc2[i][2]), u3 = unpack2(acc2[i][3]);
        float4 o0 = make_float4(fmaxf(u0.x, 0.f), fmaxf(u0.y, 0.f), fmaxf(u1.x, 0.f), fmaxf(u1.y, 0.f));
        float4 o1 = make_float4(fmaxf(u2.x, 0.f), fmaxf(u2.y, 0.f), fmaxf(u3.x, 0.f), fmaxf(u3.y, 0.f));
        *(float4*)(g_hidden + (size_t)(t0 + r) * RDIM + tx * 4) = o0;
        *(float4*)(g_hidden + (size_t)(t0 + r) * RDIM + 64 + tx * 4) = o1;
    }
    if (tid < 128) {
        float zc = cacc + bc[0];
        float c = 1.f / (1.f + expf(-zc));
        float bf = 4.f + 28.f * c * c;
        int b = (int)floorf(bf);
        g_budget[t0 + tid] = b;
        out_b[t0 + tid] = (float)b;
    }
}

// ---------------- K2: scores = hidden @ W_s + b_s ----------------
__global__ __launch_bounds__(256) void k_scores(const float* __restrict__ Wsg,
                                                const float* __restrict__ bs)
{
    extern __shared__ float sm[];
    float* Hs = sm;                 // [128][132] transposed hidden
    float* Wt = sm + 128 * 132;     // [128][132] W_s tile

    const int tid = threadIdx.x;
    const int tx = tid & 15, ty = tid >> 4;
    const int t0 = blockIdx.x * 128;

#pragma unroll
    for (int i = 0; i < 16; i++) {
        int id = tid + i * 256;
        int token = id >> 5, kg = id & 31;
        float4 f = *(const float4*)(g_hidden + (size_t)(t0 + token) * RDIM + kg * 4);
        Hs[(kg * 4 + 0) * 132 + token] = f.x;
        Hs[(kg * 4 + 1) * 132 + token] = f.y;
        Hs[(kg * 4 + 2) * 132 + token] = f.z;
        Hs[(kg * 4 + 3) * 132 + token] = f.w;
    }

    for (int nt = 0; nt < 32; nt++) {
        __syncthreads();
#pragma unroll
        for (int i = 0; i < 16; i++) {
            int id = tid + i * 256;
            int rowk = id >> 5, ng = id & 31;
            *(float4*)&Wt[rowk * 132 + ng * 4] =
                *(const float4*)(Wsg + (size_t)rowk * NSLOT + nt * 128 + ng * 4);
        }
        __syncthreads();

        unsigned long long acc2[8][4];
        {
            unsigned long long p0 = pack2(bs[nt * 128 + tx * 4 + 0], bs[nt * 128 + tx * 4 + 1]);
            unsigned long long p1 = pack2(bs[nt * 128 + tx * 4 + 2], bs[nt * 128 + tx * 4 + 3]);
            unsigned long long p2 = pack2(bs[nt * 128 + 64 + tx * 4 + 0], bs[nt * 128 + 64 + tx * 4 + 1]);
            unsigned long long p3 = pack2(bs[nt * 128 + 64 + tx * 4 + 2], bs[nt * 128 + 64 + tx * 4 + 3]);
#pragma unroll
            for (int i = 0; i < 8; i++) { acc2[i][0] = p0; acc2[i][1] = p1; acc2[i][2] = p2; acc2[i][3] = p3; }
        }
#pragma unroll 4
        for (int k = 0; k < 128; k++) {
            float4 a0 = *(float4*)&Hs[k * 132 + ty * 4];
            float4 a1 = *(float4*)&Hs[k * 132 + 64 + ty * 4];
            ulonglong2 w01 = *(ulonglong2*)&Wt[k * 132 + tx * 4];
            ulonglong2 w23 = *(ulonglong2*)&Wt[k * 132 + 64 + tx * 4];
            float xf[8] = {a0.x, a0.y, a0.z, a0.w, a1.x, a1.y, a1.z, a1.w};
#pragma unroll
            for (int i = 0; i < 8; i++) {
                unsigned long long ad = pack2(xf[i], xf[i]);
                fma2(acc2[i][0], ad, w01.x);
                fma2(acc2[i][1], ad, w01.y);
                fma2(acc2[i][2], ad, w23.x);
                fma2(acc2[i][3], ad, w23.y);
            }
        }
#pragma unroll
        for (int i = 0; i < 8; i++) {
            int r = (i < 4) ? ty * 4 + i : 64 + ty * 4 + (i - 4);
            float* base = g_scores + (size_t)(t0 + r) * NSLOT + nt * 128;
            *(ulonglong2*)(base + tx * 4)      = make_ulonglong2(acc2[i][0], acc2[i][1]);
            *(ulonglong2*)(base + 64 + tx * 4) = make_ulonglong2(acc2[i][2], acc2[i][3]);
        }
    }
}

// ---------------- K3: per-token exact top-32 (jax tie-break), weights, m/Z, counts ----------------
// 12-bit radix pass over 4096 bins, then compacted boundary-bin exact selection by warp 0.
__global__ __launch_bounds__(256) void k_topk(float* __restrict__ out_idx,
                                              float* __restrict__ out_w)
{
    __shared__ unsigned hist[4096];
    __shared__ unsigned chunkSum[256];
    __shared__ unsigned clist[2048];     // boundary bin: (low20<<12)|(4095-idx)
    __shared__ unsigned gK[32], gI[32];  // strictly greater than boundary bin
    __shared__ unsigned selKey[32], selIdx[32];
    __shared__ float    sred[8], zred[8];
    __shared__ unsigned s_chunk, s_krem, s_d1, s_kneed, s_g, s_e;

    const int t = blockIdx.x;
    const int tid = threadIdx.x, lane = tid & 31, wid = tid >> 5;
    const float* row = g_scores + (size_t)t * NSLOT;

    float v[16]; unsigned key[16];
#pragma unroll
    for (int i = 0; i < 4; i++) {
        float4 f = *(const float4*)(row + (size_t)(tid + i * 256) * 4);
        v[i * 4 + 0] = f.x; v[i * 4 + 1] = f.y; v[i * 4 + 2] = f.z; v[i * 4 + 3] = f.w;
    }
#pragma unroll
    for (int i = 0; i < 16; i++) {
        unsigned b = __float_as_uint(v[i]);
        key[i] = b ^ ((unsigned)((int)b >> 31) | 0x80000000u);
    }

    // zero hist + counters
#pragma unroll
    for (int i = 0; i < 16; i++) hist[tid + i * 256] = 0;
    if (tid == 0) { s_g = 0; s_e = 0; }

    // block max (partial)
    float m = v[0];
#pragma unroll
    for (int i = 1; i < 16; i++) m = fmaxf(m, v[i]);
    m = warpReduceMaxF(m);
    if (lane == 0) sred[wid] = m;
    __syncthreads();                                   // hist zero + sred ready

    m = sred[0];
#pragma unroll
    for (int i = 1; i < 8; i++) m = fmaxf(m, sred[i]);

    // histogram (12-bit digit) + Z
    float z = 0.f;
#pragma unroll
    for (int i = 0; i < 16; i++) {
        atomicAdd(&hist[key[i] >> 20], 1u);
        z += __expf(v[i] - m);
    }
    z = warpReduceSumF(z);
    if (lane == 0) zred[wid] = z;
    __syncthreads();                                   // hist + zred ready

    if (tid == 0) {
        float zz = 0.f;
#pragma unroll
        for (int i = 0; i < 8; i++) zz += zred[i];
        g_m[t] = m; g_z[t] = zz;
    }
    // level A: chunk sums (16 bins each)
    {
        unsigned s = 0;
#pragma unroll
        for (int j = 0; j < 16; j++) s += hist[tid * 16 + j];
        chunkSum[tid] = s;
    }
    __syncthreads();

    // level B: warp0 finds the chunk where cumulative-from-top crosses 32
    if (wid == 0) {
        unsigned cs[8], laneSum = 0;
#pragma unroll
        for (int j = 0; j < 8; j++) { cs[j] = chunkSum[lane * 8 + j]; laneSum += cs[j]; }
        unsigned s = laneSum;
#pragma unroll
        for (int o = 1; o < 32; o <<= 1) {
            unsigned tt = __shfl_down_sync(0xffffffffu, s, o);
            if (lane + o < 32) s += tt;
        }
        unsigned run = s - laneSum;  // strictly above this lane's chunk group
#pragma unroll
        for (int j = 7; j >= 0; j--) {
            unsigned nxt = run + cs[j];
            if (run < MAXK && nxt >= MAXK) { s_chunk = (unsigned)(lane * 8 + j); s_krem = MAXK - run; }
            run = nxt;
        }
    }
    __syncthreads();

    // level C: tid0 finds the exact bin
    if (tid == 0) {
        unsigned kr = s_krem, ch = s_chunk;
        for (int b = 15; b >= 0; b--) {
            unsigned h = hist[ch * 16 + b];
            if (h >= kr) { s_d1 = ch * 16 + b; s_kneed = kr; break; }
            kr -= h;
        }
    }
    __syncthreads();
    const unsigned d1 = s_d1;

    // compaction
#pragma unroll
    for (int i = 0; i < 16; i++) {
        unsigned top = key[i] >> 20;
        unsigned idx = (unsigned)((tid + (i >> 2) * 256) * 4 + (i & 3));
        if (top > d1) {
            unsigned p = atomicAdd(&s_g, 1u);
            gK[p] = key[i]; gI[p] = idx;
        } else if (top == d1) {
            unsigned p = atomicAdd(&s_e, 1u);
            if (p < 2048) clist[p] = ((key[i] & 0xFFFFFu) << 12) | (4095u - idx);
        }
    }
    __syncthreads();

    // warp0: finish selection + sort + outputs
    if (wid == 0) {
        const unsigned nG = s_g;
        const unsigned kneed = s_kneed;
        unsigned cntE = (s_e < 2048u) ? s_e : 2048u;

        if (lane < nG) { selKey[lane] = gK[lane]; selIdx[lane] = gI[lane]; }
        __syncwarp();

        for (unsigned e = 0; e < kneed; e++) {
            unsigned long long best = 0;
            for (unsigned slot = lane; slot < cntE; slot += 32) {
                unsigned long long pv = ((unsigned long long)clist[slot] << 16) | slot;
                if (pv > best) best = pv;
            }
            best = warpReduceMaxU64(best);
            unsigned packed = (unsigned)(best >> 16);
            unsigned slot = (unsigned)(best & 0xFFFFull);
            if (lane == 0) {
                selKey[nG + e] = (d1 << 20) | (packed >> 12);
                selIdx[nG + e] = 4095u - (packed & 0xFFFu);
                clist[slot] = clist[cntE - 1];   // swap-with-last removal
            }
            cntE--;
            __syncwarp();
        }

        unsigned long long kk =
            ((unsigned long long)selKey[lane] << 32) |
            (unsigned long long)(0xFFFFFFFFu - selIdx[lane]);
#pragma unroll
        for (int k2 = 2; k2 <= 32; k2 <<= 1) {
#pragma unroll
            for (int j = k2 >> 1; j > 0; j >>= 1) {
                unsigned long long o = __shfl_xor_sync(0xffffffffu, kk, j);
                bool up = ((lane & k2) == 0);
                bool low = ((lane & j) == 0);
                unsigned long long mx = (kk > o) ? kk : o;
                unsigned long long mn = (kk > o) ? o : kk;
                kk = (up == low) ? mx : mn;   // descending
            }
        }
        unsigned keyv = (unsigned)(kk >> 32);
        unsigned idxv = 0xFFFFFFFFu - (unsigned)(kk & 0xFFFFFFFFull);
        unsigned fb = (keyv & 0x80000000u) ? (keyv ^ 0x80000000u) : ~keyv;
        float val = __uint_as_float(fb);

        int b = g_budget[t];
        float v0 = __shfl_sync(0xffffffffu, val, 0);
        bool msk = lane < b;
        float ev = msk ? __expf(val - v0) : 0.f;
        float zz = warpReduceSumF(ev);
        float w = msk ? ev / zz : 0.f;

        out_idx[t * MAXK + lane] = (float)idxv;
        out_w[t * MAXK + lane] = w;
        if (msk) atomicAdd(&g_counts[idxv], 1.0f);
    }
}

// ---------------- K4: aux partial = (N/T^2) * sum_n p_tn * counts[n] ----------------
__global__ __launch_bounds__(256) void k_aux()
{
    __shared__ float sred[8];
    const int t = blockIdx.x;
    const int tid = threadIdx.x, lane = tid & 31, wid = tid >> 5;
    const float* row = g_scores + (size_t)t * NSLOT;
    const float m = g_m[t];
    const float zi = 1.f / g_z[t];
    float s = 0.f;
#pragma unroll
    for (int i = 0; i < 4; i++) {
        int n4 = tid + i * 256;
        float4 r = *(const float4*)(row + (size_t)n4 * 4);
        float4 c = g_counts_v[n4];
        s += __expf(r.x - m) * c.x + __expf(r.y - m) * c.y
           + __expf(r.z - m) * c.z + __expf(r.w - m) * c.w;
    }
    s = warpReduceSumF(s);
    if (lane == 0) sred[wid] = s;
    __syncthreads();
    if (tid == 0) {
        float ss = 0.f;
#pragma unroll
        for (int i = 0; i < 8; i++) ss += sred[i];
        float contrib = ss * zi * ((float)NSLOT / ((float)TOK * (float)TOK));
        atomicAdd(&g_aux, contrib);
    }
}

// ---------------- K5: publish aux ----------------
__global__ void k_finish(float* __restrict__ out_aux)
{
    if (threadIdx.x == 0) out_aux[0] = g_aux;
}

// ---------------- launch ----------------
extern "C" void kernel_launch(void* const* d_in, const int* in_sizes, int n_in,
                              void* d_out, int out_size)
{
    const float* x  = (const float*)d_in[0];
    const float* Wc = (const float*)d_in[1];
    const float* bc = (const float*)d_in[2];
    const float* Wh = (const float*)d_in[3];
    const float* bh = (const float*)d_in[4];
    const float* Ws = (const float*)d_in[5];
    const float* bs = (const float*)d_in[6];

    float* out     = (float*)d_out;
    float* out_idx = out;
    float* out_w   = out + TOK * MAXK;
    float* out_b   = out + 2 * TOK * MAXK;
    float* out_aux = out + 2 * TOK * MAXK + TOK;

    const int smem2 = 2 * 128 * 132 * (int)sizeof(float);
    cudaFuncSetAttribute(k_scores, cudaFuncAttributeMaxDynamicSharedMemorySize, smem2);

    k_init<<<(NSLOT + 255) / 256, 256>>>();
    k_hidden<<<TOK / 128, 256>>>(x, Wc, bc, Wh, bh, out_b);
    k_scores<<<TOK / 128, 256, smem2>>>(Ws, bs);
    k_topk<<<TOK, 256>>>(out_idx, out_w);
    k_aux<<<TOK, 256>>>();
    k_finish<<<1, 32>>>(out_aux);
}